// round 6
// baseline (speedup 1.0000x reference)
#include <cuda_runtime.h>
#include <cuda_bf16.h>

typedef unsigned long long u64;
typedef unsigned int u32;
typedef unsigned short u16;

// ---------------- packed f32x2 helpers ----------------
__device__ __forceinline__ u64 pk2(float a, float b) {
    u64 r; asm("mov.b64 %0, {%1, %2};" : "=l"(r) : "f"(a), "f"(b)); return r;
}
__device__ __forceinline__ void upk2(u64 v, float& a, float& b) {
    asm("mov.b64 {%0, %1}, %2;" : "=f"(a), "=f"(b) : "l"(v));
}
__device__ __forceinline__ u64 f2fma(u64 a, u64 b, u64 c) {
    u64 d; asm("fma.rn.f32x2 %0, %1, %2, %3;" : "=l"(d) : "l"(a), "l"(b), "l"(c)); return d;
}
__device__ __forceinline__ u64 f2mul(u64 a, u64 b) {
    u64 d; asm("mul.rn.f32x2 %0, %1, %2;" : "=l"(d) : "l"(a), "l"(b)); return d;
}
__device__ __forceinline__ u64 f2neg(u64 a) { return a ^ 0x8000000080000000ULL; }

struct C2 { u64 r, i; };

__device__ __forceinline__ C2 cmul(const C2& a, const C2& b) {
    C2 o;
    o.r = f2fma(f2neg(a.i), b.i, f2mul(a.r, b.r));
    o.i = f2fma(a.i, b.r, f2mul(a.r, b.i));
    return o;
}
__device__ __forceinline__ C2 cmulc(u64 ur, u64 ui, u64 uni, const C2& z) {
    C2 o;
    o.r = f2fma(uni, z.i, f2mul(ur, z.r));
    o.i = f2fma(ur, z.i, f2mul(ui, z.r));
    return o;
}
__device__ __forceinline__ void cfmac(C2& acc, u64 ur, u64 ui, u64 uni, const C2& z) {
    acc.r = f2fma(ur, z.r, acc.r);
    acc.r = f2fma(uni, z.i, acc.r);
    acc.i = f2fma(ui, z.r, acc.i);
    acc.i = f2fma(ur, z.i, acc.i);
}

__device__ __forceinline__ u32 smem_u32(const void* p) {
    u32 a;
    asm("{ .reg .u64 t; cvta.to.shared.u64 t, %1; cvt.u32.u64 %0, t; }" : "=r"(a) : "l"(p));
    return a;
}

// rn bf16 bits (manual, toolchain-safe)
__device__ __forceinline__ u16 bfbits(float f) {
    u32 u = __float_as_uint(f);
    u32 r = u + 0x7fffu + ((u >> 16) & 1u);
    return (u16)(r >> 16);
}
__device__ __forceinline__ float bf2f(u16 b) { return __uint_as_float(((u32)b) << 16); }

__device__ __forceinline__ int permf(int j) {
    int q0 = (j >> 3) & 1, q1 = (j >> 2) & 1, q2 = (j >> 1) & 1, q3 = j & 1;
    int n1 = q1 ^ q0, n2 = q2 ^ n1, n3 = q3 ^ n2, n0 = q0 ^ n3;
    return (n0 << 3) | (n1 << 2) | (n2 << 1) | n3;
}

// ---------------- warp-mma primitives ----------------
__device__ __forceinline__ void mma16816(float* c, const u32* a, uint2 b) {
    asm("mma.sync.aligned.m16n8k16.row.col.f32.bf16.bf16.f32 "
        "{%0,%1,%2,%3}, {%4,%5,%6,%7}, {%8,%9}, {%0,%1,%2,%3};"
        : "+f"(c[0]), "+f"(c[1]), "+f"(c[2]), "+f"(c[3])
        : "r"(a[0]), "r"(a[1]), "r"(a[2]), "r"(a[3]), "r"(b.x), "r"(b.y));
}
__device__ __forceinline__ void ldmA(u32* a, u32 addr) {
    asm volatile("ldmatrix.sync.aligned.m8n8.x4.shared.b16 {%0,%1,%2,%3}, [%4];"
        : "=r"(a[0]), "=r"(a[1]), "=r"(a[2]), "=r"(a[3]) : "r"(addr) : "memory");
}

// 32 fp32 -> row of 64 bf16 [hi(32)|lo(32)], XOR-swizzled 16B chunks, stride 128B
__device__ __forceinline__ void storeRow(const float* v, char* base, int r) {
    u32 hw[16], lw[16];
#pragma unroll
    for (int i = 0; i < 16; i++) {
        float v0 = v[2 * i], v1 = v[2 * i + 1];
        u32 b0 = __float_as_uint(v0), b1 = __float_as_uint(v1);
        hw[i] = __byte_perm(b0, b1, 0x7632);             // truncated bf16 pair
        float r0 = v0 - __uint_as_float(b0 & 0xFFFF0000u);
        float r1 = v1 - __uint_as_float(b1 & 0xFFFF0000u);
        lw[i] = __byte_perm(__float_as_uint(r0), __float_as_uint(r1), 0x7632);
    }
    char* rp = base + r * 128;
    int rx = r & 7;
#pragma unroll
    for (int c = 0; c < 4; c++)
        *(uint4*)(rp + ((c ^ rx) << 4)) = make_uint4(hw[4*c], hw[4*c+1], hw[4*c+2], hw[4*c+3]);
#pragma unroll
    for (int c = 4; c < 8; c++) {
        int i = 4 * (c - 4);
        *(uint4*)(rp + ((c ^ rx) << 4)) = make_uint4(lw[i], lw[i+1], lw[i+2], lw[i+3]);
    }
}

// ---------------- fused persistent kernel ----------------
__global__ void __launch_bounds__(128, 5) qlayer_mma(const float* __restrict__ x,
                                                     float* __restrict__ out,
                                                     const float* __restrict__ qw,
                                                     int nGroups) {
    __shared__ __align__(128) char sA[4][8192];   // per-warp 64 rows x 128B
    __shared__ uint2 sBF[16][32];
    __shared__ u64 sg[48];

    int tid = threadIdx.x, lane = tid & 31, wid = tid >> 5;

    // ======== per-block prep (warp 0), scratch aliased over A tiles ========
    if (wid == 0) {
        float2 (*sG)[4] = (float2(*)[4])(sA[0]);       // 384 B
        float* Wsm = (float*)(sA[1]);                   // 32*32*4 = 4 KB
        if (lane < 12) {
            float phi = qw[3 * lane], th = qw[3 * lane + 1], om = qw[3 * lane + 2];
            float s, c; sincosf(0.5f * th, &s, &c);
            float a = 0.5f * (phi + om), b = 0.5f * (phi - om);
            float sa, ca, sb, cb;
            sincosf(a, &sa, &ca); sincosf(b, &sb, &cb);
            sG[lane][0] = make_float2( c * ca, -c * sa);
            sG[lane][1] = make_float2(-s * cb, -s * sb);
            sG[lane][2] = make_float2( s * cb, -s * sb);
            sG[lane][3] = make_float2( c * ca,  c * sa);
        }
        __syncwarp();
        if (lane < 4) {
#pragma unroll
            for (int e = 0; e < 4; e++) {
                float re = sG[lane][e].x, im = sG[lane][e].y;
                sg[lane * 12 + e * 3 + 0] = pk2(re, re);
                sg[lane * 12 + e * 3 + 1] = pk2(im, im);
                sg[lane * 12 + e * 3 + 2] = pk2(-im, -im);
            }
        }
        if (lane < 16) {
            // evolve basis column `lane` through P1,G1,P2,G2,P3 -> column of U
            float2 col[16], tmp[16];
            for (int j = 0; j < 16; j++) col[j] = make_float2(0.f, 0.f);
            col[permf(lane)] = make_float2(1.f, 0.f);
            for (int l = 1; l <= 2; l++) {
                for (int q = 0; q < 4; q++) {
                    int s = 8 >> q;
                    float2 u00 = sG[l*4+q][0], u01 = sG[l*4+q][1];
                    float2 u10 = sG[l*4+q][2], u11 = sG[l*4+q][3];
                    for (int j = 0; j < 16; j++) if (!(j & s)) {
                        float2 a = col[j], b = col[j | s];
                        float2 nj = make_float2(u00.x*a.x - u00.y*a.y + u01.x*b.x - u01.y*b.y,
                                                u00.x*a.y + u00.y*a.x + u01.x*b.y + u01.y*b.x);
                        float2 ns = make_float2(u10.x*a.x - u10.y*a.y + u11.x*b.x - u11.y*b.y,
                                                u10.x*a.y + u10.y*a.x + u11.x*b.y + u11.y*b.x);
                        col[j] = nj; col[j|s] = ns;
                    }
                }
                for (int j = 0; j < 16; j++) tmp[permf(j)] = col[j];
                for (int j = 0; j < 16; j++) col[j] = tmp[j];
            }
            // W real 32x32: [[Ur,-Ui],[Ui,Ur]]; this thread owns cols lane, lane+16
            for (int n = 0; n < 16; n++) {
                Wsm[n * 32 + lane]              =  col[n].x;
                Wsm[(n + 16) * 32 + lane]       =  col[n].y;
                Wsm[n * 32 + lane + 16]         = -col[n].y;
                Wsm[(n + 16) * 32 + lane + 16]  =  col[n].x;
            }
        }
        __syncwarp();
        // per-lane mma.sync B fragments (k16n8 col-major); B[k][n] = W[n][k]
        {
            int t = lane & 3, g = lane >> 2;
            for (int kt = 0; kt < 2; kt++)
                for (int nt = 0; nt < 4; nt++) {
                    int n = nt * 8 + g;
                    int k0 = kt * 16 + 2 * t;
                    int ks[4] = {k0, k0 + 1, k0 + 8, k0 + 9};
                    u16 hb[4], lb[4];
                    for (int i = 0; i < 4; i++) {
                        float w = Wsm[n * 32 + ks[i]];
                        hb[i] = bfbits(w);
                        lb[i] = bfbits(w - bf2f(hb[i]));
                    }
                    sBF[kt*4+nt][lane]   = make_uint2((u32)hb[0] | ((u32)hb[1] << 16),
                                                      (u32)hb[2] | ((u32)hb[3] << 16));
                    sBF[8+kt*4+nt][lane] = make_uint2((u32)lb[0] | ((u32)lb[1] << 16),
                                                      (u32)lb[2] | ((u32)lb[3] << 16));
                }
        }
    }
    __syncthreads();

    u32 aBase = smem_u32(sA[wid]);
    char* aPtr = sA[wid];
    const float PI_F = 3.14159265358979323846f;
    const int t4 = lane & 3;
    const int rbase = lane & 15;
    const int khalf = (lane >> 4) & 1;

    // loop-invariant B fragments
    uint2 bf[16];
#pragma unroll
    for (int f = 0; f < 16; f++) bf[f] = sBF[f][lane];

    for (int grp = blockIdx.x; grp < nGroups; grp += gridDim.x) {
        int s0 = grp * 256 + wid * 64 + lane;

        // ---- product state after encoding + layer-0 Rot (2 samples, f32x2) ----
        float4 xa = ((const float4*)x)[s0];
        float4 xb = ((const float4*)x)[s0 + 32];
        float xA[4] = {xa.x, xa.y, xa.z, xa.w};
        float xB[4] = {xb.x, xb.y, xb.z, xb.w};

        C2 v[4][2];
#pragma unroll
        for (int q = 0; q < 4; q++) {
            float br0[2], bi0[2], br1[2], bi1[2];
#pragma unroll
            for (int smp = 0; smp < 2; smp++) {
                float xv = smp ? xB[q] : xA[q];
                float ex = __expf(2.0f * xv);
                float tnh = 1.0f - 2.0f / (ex + 1.0f);
                float xn = PI_F * tnh;
                float sh, ch;
                __sincosf(0.5f * xn, &sh, &ch);
                float sx = 2.0f * sh * ch;          // sin(xn)
                float cx = 1.0f - 2.0f * sh * sh;   // cos(xn)
                br0[smp] = cx * ch;  bi0[smp] = -cx * sh;
                br1[smp] = sx * ch;  bi1[smp] =  sx * sh;
            }
            C2 b0p, b1p;
            b0p.r = pk2(br0[0], br0[1]); b0p.i = pk2(bi0[0], bi0[1]);
            b1p.r = pk2(br1[0], br1[1]); b1p.i = pk2(bi1[0], bi1[1]);
            const u64* G = &sg[q * 12];
            v[q][0] = cmulc(G[0], G[1], G[2], b0p); cfmac(v[q][0], G[3], G[4], G[5], b1p);
            v[q][1] = cmulc(G[6], G[7], G[8], b0p); cfmac(v[q][1], G[9], G[10], G[11], b1p);
        }
        C2 u01[4], u23[4], st[16];
#pragma unroll
        for (int a = 0; a < 2; a++)
#pragma unroll
            for (int b = 0; b < 2; b++) {
                u01[a * 2 + b] = cmul(v[0][a], v[1][b]);
                u23[a * 2 + b] = cmul(v[2][a], v[3][b]);
            }
#pragma unroll
        for (int p = 0; p < 4; p++)
#pragma unroll
            for (int qq = 0; qq < 4; qq++)
                st[p * 4 + qq] = cmul(u01[p], u23[qq]);

        // ---- unpack, split, store A rows ----
        float vA[32], vB[32];
#pragma unroll
        for (int j = 0; j < 16; j++) {
            upk2(st[j].r, vA[j], vB[j]);
            upk2(st[j].i, vA[16 + j], vB[16 + j]);
        }
        storeRow(vA, aPtr, lane);
        storeRow(vB, aPtr, lane + 32);
        __syncwarp();

#pragma unroll
        for (int mt = 0; mt < 4; mt++) {
            int r = mt * 16 + rbase;
            u32 rowAddr = aBase + (u32)(r * 128);
            int rx = r & 7;
            u32 fr[4][4];
#pragma unroll
            for (int kt = 0; kt < 4; kt++)
                ldmA(fr[kt], rowAddr + (u32)(((kt * 2 + khalf) ^ rx) << 4));

            float acc[4][4];
#pragma unroll
            for (int nt = 0; nt < 4; nt++)
                acc[nt][0] = acc[nt][1] = acc[nt][2] = acc[nt][3] = 0.f;
#pragma unroll
            for (int nt = 0; nt < 4; nt++) {
                mma16816(acc[nt], fr[0], bf[nt]);        // hi * Whi (k 0..15)
                mma16816(acc[nt], fr[1], bf[4 + nt]);    // hi * Whi (k 16..31)
                mma16816(acc[nt], fr[2], bf[nt]);        // lo * Whi
                mma16816(acc[nt], fr[3], bf[4 + nt]);
                mma16816(acc[nt], fr[0], bf[8 + nt]);    // hi * Wlo
                mma16816(acc[nt], fr[1], bf[12 + nt]);
            }

            // ---- epilogue: p_j = Re^2+Im^2 (cols j and j+16 both local), signed Z sums ----
            float p1a = fmaf(acc[0][0], acc[0][0], acc[2][0] * acc[2][0]);  // j=2t
            float p2a = fmaf(acc[0][1], acc[0][1], acc[2][1] * acc[2][1]);  // j=2t+1
            float p3a = fmaf(acc[1][0], acc[1][0], acc[3][0] * acc[3][0]);  // j=2t+8
            float p4a = fmaf(acc[1][1], acc[1][1], acc[3][1] * acc[3][1]);  // j=2t+9
            float p1b = fmaf(acc[0][2], acc[0][2], acc[2][2] * acc[2][2]);  // row g+8
            float p2b = fmaf(acc[0][3], acc[0][3], acc[2][3] * acc[2][3]);
            float p3b = fmaf(acc[1][2], acc[1][2], acc[3][2] * acc[3][2]);
            float p4b = fmaf(acc[1][3], acc[1][3], acc[3][3] * acc[3][3]);

            float Sa = (p1a + p2a) + (p3a + p4a), Sb = (p1b + p2b) + (p3b + p4b);
            float e0a = (p1a + p2a) - (p3a + p4a), e0b = (p1b + p2b) - (p3b + p4b);
            float e3a = (p1a - p2a) + (p3a - p4a), e3b = (p1b - p2b) + (p3b - p4b);
            float e1a = (t4 < 2) ? Sa : -Sa,  e1b = (t4 < 2) ? Sb : -Sb;
            float e2a = (t4 & 1) ? -Sa : Sa,  e2b = (t4 & 1) ? -Sb : Sb;

#pragma unroll
            for (int m = 1; m <= 2; m <<= 1) {
                e0a += __shfl_xor_sync(0xffffffffu, e0a, m);
                e1a += __shfl_xor_sync(0xffffffffu, e1a, m);
                e2a += __shfl_xor_sync(0xffffffffu, e2a, m);
                e3a += __shfl_xor_sync(0xffffffffu, e3a, m);
                e0b += __shfl_xor_sync(0xffffffffu, e0b, m);
                e1b += __shfl_xor_sync(0xffffffffu, e1b, m);
                e2b += __shfl_xor_sync(0xffffffffu, e2b, m);
                e3b += __shfl_xor_sync(0xffffffffu, e3b, m);
            }
            if (t4 == mt) {
                int row0 = grp * 256 + wid * 64 + mt * 16 + (lane >> 2);
                ((float4*)out)[row0]     = make_float4(e0a, e1a, e2a, e3a);
                ((float4*)out)[row0 + 8] = make_float4(e0b, e1b, e2b, e3b);
            }
        }
        __syncwarp();   // ldmatrix reads done before next iteration's stores
    }
}

extern "C" void kernel_launch(void* const* d_in, const int* in_sizes, int n_in,
                              void* d_out, int out_size) {
    const float* x  = (const float*)d_in[0];   // [B, 4]
    const float* qw = (const float*)d_in[1];   // [3, 4, 3]
    float* out = (float*)d_out;                // [B, 4]
    int B = in_sizes[0] / 4;
    int nGroups = B / 256;
    qlayer_mma<<<740, 128>>>(x, out, qw, nGroups);
}